// round 1
// baseline (speedup 1.0000x reference)
#include <cuda_runtime.h>
#include <math.h>

#define DIMC   1024
#define NB     2
#define NSEQ   2048
#define NHEADS 16
#define NEFF   8
#define HDIM   64
#define HD2    128
#define MTOT   (NB*NSEQ)          // 4096
#define L2E    1.4426950408889634f

// ---------------- scratch (device globals; no allocations allowed) ----------
__device__ float g_lambda;
__device__ float g_q[NB*NHEADS*NSEQ*HDIM];     // [b,h,n,hd]  (pre-scaled by hd^-0.5)
__device__ float g_k[NB*NHEADS*NSEQ*HDIM];     // [b,h,n,hd]
__device__ float g_v[NB*NEFF*NSEQ*HD2];        // [b,e,n,128]
__device__ float g_attn[NB*NHEADS*NSEQ*HD2];   // per-head flash output [b,h,n,128]
__device__ float g_comb[MTOT*DIMC];            // combined+normed [b,n,1024]

// ---------------- lambda = exp(lq1.lk1) - exp(lq2.lk2) + 0.8 ----------------
__global__ void lambda_kernel(const float* __restrict__ lq1, const float* __restrict__ lk1,
                              const float* __restrict__ lq2, const float* __restrict__ lk2)
{
    int t = threadIdx.x;
    float s1 = 0.f, s2 = 0.f;
    for (int i = t; i < HDIM; i += 32) {
        s1 += lq1[i] * lk1[i];
        s2 += lq2[i] * lk2[i];
    }
    #pragma unroll
    for (int off = 16; off > 0; off >>= 1) {
        s1 += __shfl_xor_sync(0xffffffffu, s1, off);
        s2 += __shfl_xor_sync(0xffffffffu, s2, off);
    }
    if (t == 0) g_lambda = expf(s1) - expf(s2) + 0.8f;
}

// ---------------- SGEMM NT: C[m,n] = sum_k A[m,k]*W[n,k] + bias[n] ----------
// mode 0: scatter to g_q (* hd^-0.5), mode 1: g_k, mode 2: g_v, mode 3: outp
__global__ __launch_bounds__(256) void gemm_nt_kernel(const float* __restrict__ A,
                                                      const float* __restrict__ W,
                                                      const float* __restrict__ bias,
                                                      float* __restrict__ outp, int mode)
{
    __shared__ float As[16][136];
    __shared__ float Bs[16][136];
    const float* Ap = (mode == 3) ? g_comb : A;

    int m0 = blockIdx.y * 128;
    int n0 = blockIdx.x * 128;
    int t  = threadIdx.x;
    int tm = t >> 4, tn = t & 15;

    float acc[8][8];
    #pragma unroll
    for (int i = 0; i < 8; i++)
        #pragma unroll
        for (int j = 0; j < 8; j++) acc[i][j] = 0.f;

    for (int k0 = 0; k0 < DIMC; k0 += 16) {
        #pragma unroll
        for (int u = 0; u < 2; u++) {
            int id  = t + u * 256;
            int row = id >> 2;
            int c4  = (id & 3) << 2;
            float4 av = *(const float4*)(Ap + (size_t)(m0 + row) * DIMC + k0 + c4);
            As[c4+0][row] = av.x; As[c4+1][row] = av.y;
            As[c4+2][row] = av.z; As[c4+3][row] = av.w;
            float4 bv = *(const float4*)(W + (size_t)(n0 + row) * DIMC + k0 + c4);
            Bs[c4+0][row] = bv.x; Bs[c4+1][row] = bv.y;
            Bs[c4+2][row] = bv.z; Bs[c4+3][row] = bv.w;
        }
        __syncthreads();
        #pragma unroll
        for (int kk = 0; kk < 16; kk++) {
            float a[8], b[8];
            #pragma unroll
            for (int i = 0; i < 8; i++) a[i] = As[kk][tm * 8 + i];
            #pragma unroll
            for (int j = 0; j < 8; j++) b[j] = Bs[kk][tn * 8 + j];
            #pragma unroll
            for (int i = 0; i < 8; i++)
                #pragma unroll
                for (int j = 0; j < 8; j++)
                    acc[i][j] = fmaf(a[i], b[j], acc[i][j]);
        }
        __syncthreads();
    }

    #pragma unroll
    for (int i = 0; i < 8; i++) {
        int m    = m0 + tm * 8 + i;
        int bidx = m >> 11;     // / 2048
        int nn   = m & 2047;
        #pragma unroll
        for (int j = 0; j < 8; j++) {
            int n = n0 + tn * 8 + j;
            float val = acc[i][j] + bias[n];
            if (mode == 0) {
                int h = n >> 6, hd = n & 63;
                g_q[(((size_t)(bidx * NHEADS + h)) * NSEQ + nn) * HDIM + hd] = val * 0.125f;
            } else if (mode == 1) {
                int h = n >> 6, hd = n & 63;
                g_k[(((size_t)(bidx * NHEADS + h)) * NSEQ + nn) * HDIM + hd] = val;
            } else if (mode == 2) {
                int e = n >> 7, dd = n & 127;
                g_v[(((size_t)(bidx * NEFF + e)) * NSEQ + nn) * HD2 + dd] = val;
            } else {
                outp[(size_t)m * DIMC + n] = val;
            }
        }
    }
}

// ---------------- flash attention (fp32), one head per blockIdx.y ----------
// Br=64 queries, Bc=64 keys, 256 threads. S: 4x4 micro-tiles, O: 4x8.
__global__ __launch_bounds__(256) void flash_kernel()
{
    extern __shared__ float sm[];
    float* Qs = sm;               // 64*65
    float* Ks = Qs + 64 * 65;     // 64*65
    float* Vs = Ks + 64 * 65;     // 64*132
    float* Ps = Vs + 64 * 132;    // 64*65

    int qt = blockIdx.x;          // query tile (0..31)
    int bh = blockIdx.y;          // b*NHEADS + h (0..31)
    int b_ = bh >> 4;
    int h  = bh & 15;
    int e  = h >> 1;

    const float* Qg = g_q + ((size_t)bh * NSEQ + qt * 64) * HDIM;
    const float* Kg = g_k + (size_t)bh * NSEQ * HDIM;
    const float* Vg = g_v + ((size_t)(b_ * NEFF + e)) * NSEQ * HD2;

    int t  = threadIdx.x;
    int ty = t >> 4, tx = t & 15;

    // load Q tile once
    #pragma unroll
    for (int u = 0; u < 4; u++) {
        int id  = t + u * 256;
        int row = id >> 4, c = (id & 15) << 2;
        float4 v = *(const float4*)(Qg + row * HDIM + c);
        Qs[row*65+c+0] = v.x; Qs[row*65+c+1] = v.y;
        Qs[row*65+c+2] = v.z; Qs[row*65+c+3] = v.w;
    }

    float m_run[4], l_run[4], o[4][8];
    #pragma unroll
    for (int i = 0; i < 4; i++) {
        m_run[i] = -1e30f; l_run[i] = 0.f;
        #pragma unroll
        for (int j = 0; j < 8; j++) o[i][j] = 0.f;
    }

    for (int kt = 0; kt < NSEQ / 64; kt++) {
        __syncthreads();   // protects Ks/Vs (loads below) and Ps (PV reads of prev iter)
        #pragma unroll
        for (int u = 0; u < 4; u++) {
            int id  = t + u * 256;
            int row = id >> 4, c = (id & 15) << 2;
            float4 v = *(const float4*)(Kg + (size_t)(kt * 64 + row) * HDIM + c);
            Ks[row*65+c+0] = v.x; Ks[row*65+c+1] = v.y;
            Ks[row*65+c+2] = v.z; Ks[row*65+c+3] = v.w;
        }
        #pragma unroll
        for (int u = 0; u < 8; u++) {
            int id  = t + u * 256;
            int row = id >> 5, c = (id & 31) << 2;
            float4 v = *(const float4*)(Vg + (size_t)(kt * 64 + row) * HD2 + c);
            Vs[row*132+c+0] = v.x; Vs[row*132+c+1] = v.y;
            Vs[row*132+c+2] = v.z; Vs[row*132+c+3] = v.w;
        }
        __syncthreads();

        // S = Q K^T  (4x4 per thread)
        float s[4][4];
        #pragma unroll
        for (int i = 0; i < 4; i++)
            #pragma unroll
            for (int j = 0; j < 4; j++) s[i][j] = 0.f;
        #pragma unroll 8
        for (int kk = 0; kk < HDIM; kk++) {
            float qv[4], kv[4];
            #pragma unroll
            for (int i = 0; i < 4; i++) qv[i] = Qs[(ty*4+i)*65 + kk];
            #pragma unroll
            for (int j = 0; j < 4; j++) kv[j] = Ks[(tx*4+j)*65 + kk];
            #pragma unroll
            for (int i = 0; i < 4; i++)
                #pragma unroll
                for (int j = 0; j < 4; j++)
                    s[i][j] = fmaf(qv[i], kv[j], s[i][j]);
        }

        // online softmax per row (rows owned by 16 tx-lanes, contiguous 16-lane groups)
        #pragma unroll
        for (int i = 0; i < 4; i++) {
            float mt = s[i][0];
            #pragma unroll
            for (int j = 1; j < 4; j++) mt = fmaxf(mt, s[i][j]);
            #pragma unroll
            for (int off = 8; off > 0; off >>= 1)
                mt = fmaxf(mt, __shfl_xor_sync(0xffffffffu, mt, off, 16));
            float m_new = fmaxf(m_run[i], mt);
            float alpha = exp2f((m_run[i] - m_new) * L2E);
            float rs = 0.f;
            #pragma unroll
            for (int j = 0; j < 4; j++) {
                s[i][j] = exp2f((s[i][j] - m_new) * L2E);
                rs += s[i][j];
            }
            #pragma unroll
            for (int off = 8; off > 0; off >>= 1)
                rs += __shfl_xor_sync(0xffffffffu, rs, off, 16);
            l_run[i] = l_run[i] * alpha + rs;
            m_run[i] = m_new;
            #pragma unroll
            for (int j = 0; j < 8; j++) o[i][j] *= alpha;
            #pragma unroll
            for (int j = 0; j < 4; j++) Ps[(ty*4+i)*65 + tx*4 + j] = s[i][j];
        }
        __syncthreads();

        // O += P V  (4 rows x 8 cols per thread; cols = tx*8..tx*8+7)
        #pragma unroll 8
        for (int kk = 0; kk < 64; kk++) {
            float pr[4], vv[8];
            #pragma unroll
            for (int i = 0; i < 4; i++) pr[i] = Ps[(ty*4+i)*65 + kk];
            #pragma unroll
            for (int j = 0; j < 8; j++) vv[j] = Vs[kk*132 + tx*8 + j];
            #pragma unroll
            for (int i = 0; i < 4; i++)
                #pragma unroll
                for (int j = 0; j < 8; j++)
                    o[i][j] = fmaf(pr[i], vv[j], o[i][j]);
        }
    }

    float* Og = g_attn + ((size_t)bh * NSEQ + qt * 64) * HD2;
    #pragma unroll
    for (int i = 0; i < 4; i++) {
        float inv = 1.f / l_run[i];
        #pragma unroll
        for (int j = 0; j < 8; j++)
            Og[(size_t)(ty*4+i) * HD2 + tx*8 + j] = o[i][j] * inv;
    }
}

// ---------------- combine: o0 - lam*o1, headwise RMSNorm(128), *w*0.2 -------
__global__ __launch_bounds__(128) void combine_kernel(const float* __restrict__ norm_w)
{
    int idx = blockIdx.x;                  // (b*NEFF + e)*NSEQ + n
    int n   = idx & (NSEQ - 1);
    int be  = idx >> 11;
    int b_  = be >> 3, e = be & 7;
    int d   = threadIdx.x;                 // 0..127
    float lam = g_lambda;

    size_t base0 = (((size_t)(b_ * NHEADS + 2 * e    )) * NSEQ + n) * HD2;
    size_t base1 = (((size_t)(b_ * NHEADS + 2 * e + 1)) * NSEQ + n) * HD2;
    float xv = g_attn[base0 + d] - lam * g_attn[base1 + d];

    float ss = xv * xv;
    #pragma unroll
    for (int off = 16; off > 0; off >>= 1)
        ss += __shfl_xor_sync(0xffffffffu, ss, off);
    __shared__ float red[4];
    if ((d & 31) == 0) red[d >> 5] = ss;
    __syncthreads();
    float tot = red[0] + red[1] + red[2] + red[3];
    float rms = rsqrtf(tot * (1.0f / HD2) + 1e-5f);

    g_comb[((size_t)(b_ * NSEQ + n)) * DIMC + e * HD2 + d] = xv * rms * norm_w[d] * 0.2f;
}

// ---------------- launch -----------------------------------------------------
extern "C" void kernel_launch(void* const* d_in, const int* in_sizes, int n_in,
                              void* d_out, int out_size)
{
    const float* x      = (const float*)d_in[0];
    const float* Wq     = (const float*)d_in[1];
    const float* bq     = (const float*)d_in[2];
    const float* Wk     = (const float*)d_in[3];
    const float* bk     = (const float*)d_in[4];
    const float* Wv     = (const float*)d_in[5];
    const float* bv     = (const float*)d_in[6];
    const float* Wo     = (const float*)d_in[7];
    const float* bo     = (const float*)d_in[8];
    const float* norm_w = (const float*)d_in[9];
    const float* lq1    = (const float*)d_in[10];
    const float* lk1    = (const float*)d_in[11];
    const float* lq2    = (const float*)d_in[12];
    const float* lk2    = (const float*)d_in[13];
    float* out = (float*)d_out;

    lambda_kernel<<<1, 32>>>(lq1, lk1, lq2, lk2);

    dim3 gg(DIMC / 128, MTOT / 128);   // (8, 32)
    gemm_nt_kernel<<<gg, 256>>>(x, Wq, bq, nullptr, 0);
    gemm_nt_kernel<<<gg, 256>>>(x, Wk, bk, nullptr, 1);
    gemm_nt_kernel<<<gg, 256>>>(x, Wv, bv, nullptr, 2);

    int smem_bytes = (64 * 65 * 3 + 64 * 132) * (int)sizeof(float);  // ~84 KB
    cudaFuncSetAttribute(flash_kernel, cudaFuncAttributeMaxDynamicSharedMemorySize, smem_bytes);
    flash_kernel<<<dim3(NSEQ / 64, NB * NHEADS), 256, smem_bytes>>>();

    combine_kernel<<<NB * NEFF * NSEQ, 128>>>(norm_w);

    gemm_nt_kernel<<<gg, 256>>>(nullptr, Wo, bo, out, 3);
}

// round 5
// speedup vs baseline: 2.4902x; 2.4902x over previous
#include <cuda_runtime.h>
#include <math.h>
#include <stdint.h>

#define DIMC   1024
#define NB     2
#define NSEQ   2048
#define NHEADS 16
#define NEFF   8
#define HDIM   64
#define HD2    128
#define MTOT   (NB*NSEQ)          // 4096
#define L2E    1.4426950408889634f

// ---------------- scratch (device globals; no allocations allowed) ----------
__device__ float g_lambda;
__device__ float g_q[NB*NHEADS*NSEQ*HDIM];     // [b,h,n,hd] (pre-scaled, tf32-rounded)
__device__ float g_k[NB*NHEADS*NSEQ*HDIM];     // [b,h,n,hd]
__device__ float g_v[NB*NEFF*NSEQ*HD2];        // [b,e,n,128]
__device__ float g_attn[NB*NHEADS*NSEQ*HD2];   // per-head flash output
__device__ float g_comb[MTOT*DIMC];            // combined+normed [b,n,1024]

// ==================== helpers ======================
__device__ __forceinline__ uint32_t smem_u32(const void* p) {
    uint32_t a;
    asm("{ .reg .u64 t; cvta.to.shared.u64 t, %1; cvt.u32.u64 %0, t; }" : "=r"(a) : "l"(p));
    return a;
}
__device__ __forceinline__ float f2tf(float x) {   // round-to-nearest-even tf32
    uint32_t r;
    asm("cvt.rna.tf32.f32 %0, %1;" : "=r"(r) : "f"(x));
    return __uint_as_float(r);
}
__device__ __forceinline__ uint32_t fb(float x) { return __float_as_uint(x); }

// m16n8k8 tf32 mma: D += A(row) * B(col)
__device__ __forceinline__ void mma8(float* d, const uint32_t* a, uint32_t b0, uint32_t b1) {
    asm volatile("mma.sync.aligned.m16n8k8.row.col.f32.tf32.tf32.f32 "
                 "{%0,%1,%2,%3}, {%4,%5,%6,%7}, {%8,%9}, {%0,%1,%2,%3};"
                 : "+f"(d[0]), "+f"(d[1]), "+f"(d[2]), "+f"(d[3])
                 : "r"(a[0]), "r"(a[1]), "r"(a[2]), "r"(a[3]), "r"(b0), "r"(b1));
}

#define CP_ASYNC16(dst, src) \
    asm volatile("cp.async.cg.shared.global [%0], [%1], 16;" :: "r"(dst), "l"(src) : "memory")
#define CP_COMMIT() asm volatile("cp.async.commit_group;" ::: "memory")
#define CP_WAIT1()  asm volatile("cp.async.wait_group 1;" ::: "memory")

// ---------------- lambda = exp(lq1.lk1) - exp(lq2.lk2) + 0.8 ----------------
__global__ void lambda_kernel(const float* __restrict__ lq1, const float* __restrict__ lk1,
                              const float* __restrict__ lq2, const float* __restrict__ lk2)
{
    int t = threadIdx.x;
    float s1 = 0.f, s2 = 0.f;
    for (int i = t; i < HDIM; i += 32) {
        s1 += lq1[i] * lk1[i];
        s2 += lq2[i] * lk2[i];
    }
    #pragma unroll
    for (int off = 16; off > 0; off >>= 1) {
        s1 += __shfl_xor_sync(0xffffffffu, s1, off);
        s2 += __shfl_xor_sync(0xffffffffu, s2, off);
    }
    if (t == 0) g_lambda = expf(s1) - expf(s2) + 0.8f;
}

// ============ tf32 mma.sync GEMM NT: C[m,n] = sum_k A[m,k]*W[n,k] + bias[n] ==
// 128 threads (4 warps), CTA 128x128, warp 64x64 (4m x 8n atoms), K-chunk 32.
// mode 0: g_q (*0.125), 1: g_k, 2: g_v, 3: outp
__global__ __launch_bounds__(128) void gemm_mma_kernel(const float* __restrict__ A,
                                                       const float* __restrict__ W,
                                                       const float* __restrict__ bias,
                                                       float* __restrict__ outp, int mode)
{
    __shared__ float As[128 * 36];
    __shared__ float Bs[128 * 36];

    const float* Ap = (mode == 3) ? g_comb : A;
    int m0 = blockIdx.y * 128;
    int n0 = blockIdx.x * 128;
    int tid = threadIdx.x, wid = tid >> 5, lane = tid & 31;
    int wm = wid >> 1, wn = wid & 1;
    int g = lane >> 2, tg = lane & 3;

    float acc[4][8][4];
    #pragma unroll
    for (int mi = 0; mi < 4; mi++)
        #pragma unroll
        for (int ni = 0; ni < 8; ni++)
            #pragma unroll
            for (int j = 0; j < 4; j++) acc[mi][ni][j] = 0.f;

    for (int c = 0; c < 32; c++) {
        __syncthreads();
        int k0 = c * 32;
        #pragma unroll
        for (int i = 0; i < 8; i++) {
            int idx = tid + i * 128;
            int row = idx >> 3, c4 = (idx & 7) * 4;
            float4 av = *(const float4*)(Ap + (size_t)(m0 + row) * DIMC + k0 + c4);
            float4 bv = *(const float4*)(W  + (size_t)(n0 + row) * DIMC + k0 + c4);
            float* pa = As + row * 36 + c4;
            float* pb = Bs + row * 36 + c4;
            *(float2*)(pa)     = make_float2(f2tf(av.x), f2tf(av.y));
            *(float2*)(pa + 2) = make_float2(f2tf(av.z), f2tf(av.w));
            *(float2*)(pb)     = make_float2(f2tf(bv.x), f2tf(bv.y));
            *(float2*)(pb + 2) = make_float2(f2tf(bv.z), f2tf(bv.w));
        }
        __syncthreads();
        #pragma unroll
        for (int kk = 0; kk < 4; kk++) {
            uint32_t a[4][4];
            #pragma unroll
            for (int mi = 0; mi < 4; mi++) {
                const float* base = As + (wm * 64 + mi * 16 + g) * 36 + kk * 8 + tg;
                a[mi][0] = fb(base[0]);
                a[mi][1] = fb(base[8 * 36]);
                a[mi][2] = fb(base[4]);
                a[mi][3] = fb(base[8 * 36 + 4]);
            }
            #pragma unroll
            for (int ni = 0; ni < 8; ni++) {
                const float* bbase = Bs + (wn * 64 + ni * 8 + g) * 36 + kk * 8 + tg;
                uint32_t b0 = fb(bbase[0]);
                uint32_t b1 = fb(bbase[4]);
                #pragma unroll
                for (int mi = 0; mi < 4; mi++)
                    mma8(acc[mi][ni], a[mi], b0, b1);
            }
        }
    }

    // epilogue: scatter with bias
    #pragma unroll
    for (int mi = 0; mi < 4; mi++) {
        int m = m0 + wm * 64 + mi * 16 + g;
        #pragma unroll
        for (int ni = 0; ni < 8; ni++) {
            int n = n0 + wn * 64 + ni * 8 + tg * 2;
            float2 bs2 = *(const float2*)(bias + n);
            #pragma unroll
            for (int half = 0; half < 2; half++) {
                int mm = m + half * 8;
                float x = acc[mi][ni][half * 2 + 0] + bs2.x;
                float y = acc[mi][ni][half * 2 + 1] + bs2.y;
                int b_ = mm >> 11, nn = mm & 2047;
                if (mode == 0) {
                    int h = n >> 6, hd = n & 63;
                    *(float2*)(g_q + (((size_t)(b_*NHEADS+h))*NSEQ+nn)*HDIM + hd) =
                        make_float2(f2tf(x * 0.125f), f2tf(y * 0.125f));
                } else if (mode == 1) {
                    int h = n >> 6, hd = n & 63;
                    *(float2*)(g_k + (((size_t)(b_*NHEADS+h))*NSEQ+nn)*HDIM + hd) =
                        make_float2(f2tf(x), f2tf(y));
                } else if (mode == 2) {
                    int e = n >> 7, d2 = n & 127;
                    *(float2*)(g_v + (((size_t)(b_*NEFF+e))*NSEQ+nn)*HD2 + d2) =
                        make_float2(x, y);
                } else {
                    *(float2*)(outp + (size_t)mm * DIMC + n) = make_float2(x, y);
                }
            }
        }
    }
}

// ---------------- flash attention, tf32 mma.sync ----------------------------
// Br=128 q-rows, Bc=64 keys, 128 threads = 4 warps, warp = 32-row stripe
// (2 m-atoms). S: 2x8 atoms; O: 2x16 atoms. V double-buffered via cp.async.
__global__ __launch_bounds__(128) void flash_kernel()
{
    extern __shared__ float sm[];
    float* Qs = sm;                     // [128][68]
    float* Ks = Qs + 128 * 68;          // [64][68]
    float* Vs = Ks + 64 * 68;           // [2][64][136]
    float* Ps = Vs + 2 * 64 * 136;      // [128][68]

    int qt = blockIdx.x;                // 0..15
    int bh = blockIdx.y;                // 0..31
    int b_ = bh >> 4, h = bh & 15, e = h >> 1;

    const float* Qg = g_q + ((size_t)bh * NSEQ + qt * 128) * HDIM;
    const float* Kg = g_k + (size_t)bh * NSEQ * HDIM;
    const float* Vg = g_v + ((size_t)(b_ * NEFF + e)) * NSEQ * HD2;

    int tid = threadIdx.x, wid = tid >> 5, lane = tid & 31;
    int g = lane >> 2, tg = lane & 3;
    uint32_t vbase = smem_u32(Vs);

    // Q load + tf32 round (Q already pre-scaled by 0.125 in gemm mode 0)
    #pragma unroll
    for (int i = 0; i < 16; i++) {
        int idx = tid + i * 128;
        int row = idx >> 4, c4 = (idx & 15) * 4;
        float4 v = *(const float4*)(Qg + row * HDIM + c4);
        *(float4*)(Qs + row * 68 + c4) = v;   // already tf32-rounded at production
    }

    // prologue: V tile 0 -> buf 0
    #pragma unroll
    for (int i = 0; i < 16; i++) {
        int idx = tid + i * 128;
        int row = idx >> 5, c4 = (idx & 31) * 4;
        CP_ASYNC16(vbase + (uint32_t)(row * 544 + c4 * 4), Vg + (size_t)row * HD2 + c4);
    }
    CP_COMMIT();

    float o[2][16][4];
    #pragma unroll
    for (int mi = 0; mi < 2; mi++)
        #pragma unroll
        for (int ni = 0; ni < 16; ni++)
            #pragma unroll
            for (int j = 0; j < 4; j++) o[mi][ni][j] = 0.f;
    float mrun[4] = {-1e30f, -1e30f, -1e30f, -1e30f};
    float lrun[4] = {0.f, 0.f, 0.f, 0.f};

    for (int kt = 0; kt < 32; kt++) {
        int buf = kt & 1;
        // prefetch V_{kt+1} into other buffer
        if (kt + 1 < 32) {
            uint32_t vb = vbase + (uint32_t)((buf ^ 1) * 64 * 544);
            #pragma unroll
            for (int i = 0; i < 16; i++) {
                int idx = tid + i * 128;
                int row = idx >> 5, c4 = (idx & 31) * 4;
                CP_ASYNC16(vb + (uint32_t)(row * 544 + c4 * 4),
                           Vg + (size_t)((kt + 1) * 64 + row) * HD2 + c4);
            }
        }
        CP_COMMIT();
        // K tile: direct load (already tf32-rounded at production)
        #pragma unroll
        for (int i = 0; i < 8; i++) {
            int idx = tid + i * 128;
            int row = idx >> 4, c4 = (idx & 15) * 4;
            float4 v = *(const float4*)(Kg + (size_t)(kt * 64 + row) * HDIM + c4);
            *(float4*)(Ks + row * 68 + c4) = v;
        }
        CP_WAIT1();
        __syncthreads();

        // ---- S = Q K^T  (warp stripe rows wid*32..+32, cols 0..64)
        float s[2][8][4];
        #pragma unroll
        for (int mi = 0; mi < 2; mi++)
            #pragma unroll
            for (int ni = 0; ni < 8; ni++)
                #pragma unroll
                for (int j = 0; j < 4; j++) s[mi][ni][j] = 0.f;
        #pragma unroll
        for (int kk = 0; kk < 8; kk++) {
            uint32_t a[2][4];
            #pragma unroll
            for (int mi = 0; mi < 2; mi++) {
                const float* base = Qs + (wid * 32 + mi * 16 + g) * 68 + kk * 8 + tg;
                a[mi][0] = fb(base[0]);
                a[mi][1] = fb(base[8 * 68]);
                a[mi][2] = fb(base[4]);
                a[mi][3] = fb(base[8 * 68 + 4]);
            }
            #pragma unroll
            for (int ni = 0; ni < 8; ni++) {
                const float* bbase = Ks + (ni * 8 + g) * 68 + kk * 8 + tg;
                uint32_t b0 = fb(bbase[0]);
                uint32_t b1 = fb(bbase[4]);
                mma8(s[0][ni], a[0], b0, b1);
                mma8(s[1][ni], a[1], b0, b1);
            }
        }

        // ---- online softmax (rows fully within warp; reduce over tg quad)
        #pragma unroll
        for (int mi = 0; mi < 2; mi++) {
            #pragma unroll
            for (int half = 0; half < 2; half++) {
                int ri = mi * 2 + half;
                float mx = -1e30f;
                #pragma unroll
                for (int ni = 0; ni < 8; ni++) {
                    mx = fmaxf(mx, s[mi][ni][half * 2 + 0]);
                    mx = fmaxf(mx, s[mi][ni][half * 2 + 1]);
                }
                mx = fmaxf(mx, __shfl_xor_sync(0xffffffffu, mx, 1));
                mx = fmaxf(mx, __shfl_xor_sync(0xffffffffu, mx, 2));
                float mnew = fmaxf(mrun[ri], mx);
                float alpha = exp2f((mrun[ri] - mnew) * L2E);
                float sum = 0.f;
                #pragma unroll
                for (int ni = 0; ni < 8; ni++) {
                    float p0 = exp2f((s[mi][ni][half * 2 + 0] - mnew) * L2E);
                    float p1 = exp2f((s[mi][ni][half * 2 + 1] - mnew) * L2E);
                    s[mi][ni][half * 2 + 0] = p0;
                    s[mi][ni][half * 2 + 1] = p1;
                    sum += p0 + p1;
                }
                sum += __shfl_xor_sync(0xffffffffu, sum, 1);
                sum += __shfl_xor_sync(0xffffffffu, sum, 2);
                lrun[ri] = lrun[ri] * alpha + sum;
                mrun[ri] = mnew;
                #pragma unroll
                for (int ni = 0; ni < 16; ni++) {
                    o[mi][ni][half * 2 + 0] *= alpha;
                    o[mi][ni][half * 2 + 1] *= alpha;
                }
                // store P row (warp-private region of Ps)
                int r = wid * 32 + mi * 16 + g + half * 8;
                #pragma unroll
                for (int ni = 0; ni < 8; ni++) {
                    *(float2*)(Ps + r * 68 + ni * 8 + tg * 2) =
                        make_float2(f2tf(s[mi][ni][half * 2 + 0]),
                                    f2tf(s[mi][ni][half * 2 + 1]));
                }
            }
        }

        // ---- O += P V  (P warp-private; V raw fp32 bits as tf32)
        const float* Vb = Vs + buf * 64 * 136;
        #pragma unroll
        for (int kk = 0; kk < 8; kk++) {
            uint32_t a[2][4];
            #pragma unroll
            for (int mi = 0; mi < 2; mi++) {
                const float* base = Ps + (wid * 32 + mi * 16 + g) * 68 + kk * 8 + tg;
                a[mi][0] = fb(base[0]);
                a[mi][1] = fb(base[8 * 68]);
                a[mi][2] = fb(base[4]);
                a[mi][3] = fb(base[8 * 68 + 4]);
            }
            #pragma unroll
            for (int ni = 0; ni < 16; ni++) {
                const float* bbase = Vb + (kk * 8 + tg) * 136 + ni * 8 + g;
                uint32_t b0 = fb(bbase[0]);
                uint32_t b1 = fb(bbase[4 * 136]);
                mma8(o[0][ni], a[0], b0, b1);
                mma8(o[1][ni], a[1], b0, b1);
            }
        }
        __syncthreads();   // all reads of Ks/Vs[buf] done before next overwrite
    }

    // epilogue
    float* Og = g_attn + ((size_t)bh * NSEQ + qt * 128) * HD2;
    #pragma unroll
    for (int mi = 0; mi < 2; mi++) {
        #pragma unroll
        for (int half = 0; half < 2; half++) {
            int ri = mi * 2 + half;
            float inv = 1.f / lrun[ri];
            int r = wid * 32 + mi * 16 + g + half * 8;
            #pragma unroll
            for (int ni = 0; ni < 16; ni++) {
                *(float2*)(Og + (size_t)r * HD2 + ni * 8 + tg * 2) =
                    make_float2(o[mi][ni][half * 2 + 0] * inv,
                                o[mi][ni][half * 2 + 1] * inv);
            }
        }
    }
}

// ---------------- combine: o0 - lam*o1, headwise RMSNorm(128), *w*0.2 -------
__global__ __launch_bounds__(128) void combine_kernel(const float* __restrict__ norm_w)
{
    int idx = blockIdx.x;
    int n   = idx & (NSEQ - 1);
    int be  = idx >> 11;
    int b_  = be >> 3, e = be & 7;
    int d   = threadIdx.x;
    float lam = g_lambda;

    size_t base0 = (((size_t)(b_ * NHEADS + 2 * e    )) * NSEQ + n) * HD2;
    size_t base1 = (((size_t)(b_ * NHEADS + 2 * e + 1)) * NSEQ + n) * HD2;
    float xv = g_attn[base0 + d] - lam * g_attn[base1 + d];

    float ss = xv * xv;
    #pragma unroll
    for (int off = 16; off > 0; off >>= 1)
        ss += __shfl_xor_sync(0xffffffffu, ss, off);
    __shared__ float red[4];
    if ((d & 31) == 0) red[d >> 5] = ss;
    __syncthreads();
    float tot = red[0] + red[1] + red[2] + red[3];
    float rms = rsqrtf(tot * (1.0f / HD2) + 1e-5f);

    g_comb[((size_t)(b_ * NSEQ + n)) * DIMC + e * HD2 + d] = xv * rms * norm_w[d] * 0.2f;
}

// ---------------- launch -----------------------------------------------------
extern "C" void kernel_launch(void* const* d_in, const int* in_sizes, int n_in,
                              void* d_out, int out_size)
{
    const float* x      = (const float*)d_in[0];
    const float* Wq     = (const float*)d_in[1];
    const float* bq     = (const float*)d_in[2];
    const float* Wk     = (const float*)d_in[3];
    const float* bk     = (const float*)d_in[4];
    const float* Wv     = (const float*)d_in[5];
    const float* bv     = (const float*)d_in[6];
    const float* Wo     = (const float*)d_in[7];
    const float* bo     = (const float*)d_in[8];
    const float* norm_w = (const float*)d_in[9];
    const float* lq1    = (const float*)d_in[10];
    const float* lk1    = (const float*)d_in[11];
    const float* lq2    = (const float*)d_in[12];
    const float* lk2    = (const float*)d_in[13];
    float* out = (float*)d_out;

    lambda_kernel<<<1, 32>>>(lq1, lk1, lq2, lk2);

    dim3 gg(DIMC / 128, MTOT / 128);   // (8, 32)
    gemm_mma_kernel<<<gg, 128>>>(x, Wq, bq, nullptr, 0);
    gemm_mma_kernel<<<gg, 128>>>(x, Wk, bk, nullptr, 1);
    gemm_mma_kernel<<<gg, 128>>>(x, Wv, bv, nullptr, 2);

    int flash_smem = (128 * 68 + 64 * 68 + 2 * 64 * 136 + 128 * 68) * (int)sizeof(float); // 156672
    cudaFuncSetAttribute(flash_kernel, cudaFuncAttributeMaxDynamicSharedMemorySize, flash_smem);
    flash_kernel<<<dim3(NSEQ / 128, NB * NHEADS), 128, flash_smem>>>();

    combine_kernel<<<NB * NEFF * NSEQ, 128>>>(norm_w);

    gemm_mma_kernel<<<gg, 128>>>(nullptr, Wo, bo, out, 3);
}

// round 7
// speedup vs baseline: 3.8151x; 1.5320x over previous
#include <cuda_runtime.h>
#include <math.h>
#include <stdint.h>

#define DIMC   1024
#define NB     2
#define NSEQ   2048
#define NHEADS 16
#define NEFF   8
#define HDIM   64
#define HD2    128
#define MTOT   (NB*NSEQ)          // 4096
#define L2E    1.4426950408889634f

// ---------------- scratch (device globals; no allocations allowed) ----------
__device__ float g_lambda;
__device__ float g_xr[MTOT*DIMC];              // tf32-rounded x
__device__ float g_wr[4][DIMC*DIMC];           // tf32-rounded Wq,Wk,Wv,Wo
__device__ float g_q[NB*NHEADS*NSEQ*HDIM];     // [b,h,n,hd] (pre-scaled, tf32-rounded)
__device__ float g_k[NB*NHEADS*NSEQ*HDIM];     // [b,h,n,hd] (tf32-rounded)
__device__ float g_v[NB*NEFF*NSEQ*HD2];        // [b,e,n,128] raw fp32
__device__ float g_attn[NB*NHEADS*NSEQ*HD2];   // per-head flash output
__device__ float g_comb[MTOT*DIMC];            // combined+normed (tf32-rounded)

// ==================== helpers ======================
__device__ __forceinline__ uint32_t smem_u32(const void* p) {
    uint32_t a;
    asm("{ .reg .u64 t; cvta.to.shared.u64 t, %1; cvt.u32.u64 %0, t; }" : "=r"(a) : "l"(p));
    return a;
}
__device__ __forceinline__ float f2tf(float x) {   // round-to-nearest tf32
    uint32_t r;
    asm("cvt.rna.tf32.f32 %0, %1;" : "=r"(r) : "f"(x));
    return __uint_as_float(r);
}
__device__ __forceinline__ uint32_t fb(float x) { return __float_as_uint(x); }

// m16n8k8 tf32 mma: D += A(row) * B(col)
__device__ __forceinline__ void mma8(float* d, const uint32_t* a, uint32_t b0, uint32_t b1) {
    asm volatile("mma.sync.aligned.m16n8k8.row.col.f32.tf32.tf32.f32 "
                 "{%0,%1,%2,%3}, {%4,%5,%6,%7}, {%8,%9}, {%0,%1,%2,%3};"
                 : "+f"(d[0]), "+f"(d[1]), "+f"(d[2]), "+f"(d[3])
                 : "r"(a[0]), "r"(a[1]), "r"(a[2]), "r"(a[3]), "r"(b0), "r"(b1));
}

#define CP_ASYNC16(dst, src) \
    asm volatile("cp.async.cg.shared.global [%0], [%1], 16;" :: "r"(dst), "l"(src) : "memory")
#define CP_COMMIT() asm volatile("cp.async.commit_group;" ::: "memory")
#define CP_WAIT1()  asm volatile("cp.async.wait_group 1;" ::: "memory")
#define CP_WAIT2()  asm volatile("cp.async.wait_group 2;" ::: "memory")

// ---------------- tf32 pre-round: dst[i] = rna_tf32(src[i]) ----------------
__global__ __launch_bounds__(256) void round_kernel(const float* __restrict__ src,
                                                    float* __restrict__ dst)
{
    int i = (blockIdx.x * 256 + threadIdx.x) * 4;
    float4 v = *(const float4*)(src + i);
    v.x = f2tf(v.x); v.y = f2tf(v.y); v.z = f2tf(v.z); v.w = f2tf(v.w);
    *(float4*)(dst + i) = v;
}

// ---------------- lambda = exp(lq1.lk1) - exp(lq2.lk2) + 0.8 ----------------
__global__ void lambda_kernel(const float* __restrict__ lq1, const float* __restrict__ lk1,
                              const float* __restrict__ lq2, const float* __restrict__ lk2)
{
    int t = threadIdx.x;
    float s1 = 0.f, s2 = 0.f;
    for (int i = t; i < HDIM; i += 32) {
        s1 += lq1[i] * lk1[i];
        s2 += lq2[i] * lk2[i];
    }
    #pragma unroll
    for (int off = 16; off > 0; off >>= 1) {
        s1 += __shfl_xor_sync(0xffffffffu, s1, off);
        s2 += __shfl_xor_sync(0xffffffffu, s2, off);
    }
    if (t == 0) g_lambda = expf(s1) - expf(s2) + 0.8f;
}

// ============ tf32 mma.sync GEMM NT, 3-stage cp.async pipeline ==============
// 256 threads (8 warps), CTA 128x128, warp 32x64 (2m x 8n atoms), K-chunk 32.
// Inputs pre-rounded to tf32 in global. mode 0: g_q(*0.125), 1: g_k, 2: g_v, 3: outp
#define SSTR (128*36)      // floats per matrix per stage

__global__ __launch_bounds__(256, 2) void gemm_mma_kernel(const float* __restrict__ A,
                                                          const float* __restrict__ W,
                                                          const float* __restrict__ bias,
                                                          float* __restrict__ outp, int mode)
{
    extern __shared__ float smem[];
    uint32_t sbase = smem_u32(smem);

    const float* Ap = (mode == 3) ? g_comb : A;
    int m0 = blockIdx.y * 128;
    int n0 = blockIdx.x * 128;
    int tid = threadIdx.x, wid = tid >> 5, lane = tid & 31;
    int wm = wid >> 1, wn = wid & 1;
    int g = lane >> 2, tg = lane & 3;

    int lrow = tid >> 3;                  // 0..31 (row step 32 over i)
    int lc4  = (tid & 7) * 4;             // 0..28

    float acc[2][8][4];
    #pragma unroll
    for (int mi = 0; mi < 2; mi++)
        #pragma unroll
        for (int ni = 0; ni < 8; ni++)
            #pragma unroll
            for (int j = 0; j < 4; j++) acc[mi][ni][j] = 0.f;

    // --- pipeline: issue chunk c into stage c%3
    #define GEMM_ISSUE(c, st) do { \
        uint32_t as = sbase + (uint32_t)((st) * 2 * SSTR) * 4u; \
        uint32_t bs = as + (uint32_t)SSTR * 4u; \
        const float* ag = Ap + (size_t)m0 * DIMC + (c) * 32; \
        const float* bg = W  + (size_t)n0 * DIMC + (c) * 32; \
        _Pragma("unroll") \
        for (int i = 0; i < 4; i++) { \
            int row = lrow + i * 32; \
            CP_ASYNC16(as + (uint32_t)(row * 36 + lc4) * 4u, ag + (size_t)row * DIMC + lc4); \
            CP_ASYNC16(bs + (uint32_t)(row * 36 + lc4) * 4u, bg + (size_t)row * DIMC + lc4); \
        } \
    } while (0)

    GEMM_ISSUE(0, 0); CP_COMMIT();
    GEMM_ISSUE(1, 1); CP_COMMIT();

    int st = 0;
    for (int c = 0; c < 32; c++) {
        int st2 = st + 2 >= 3 ? st - 1 : st + 2;
        if (c + 2 < 32) GEMM_ISSUE(c + 2, st2);
        CP_COMMIT();
        CP_WAIT2();
        __syncthreads();

        const float* As = smem + st * 2 * SSTR;
        const float* Bs = As + SSTR;
        #pragma unroll
        for (int kk = 0; kk < 4; kk++) {
            uint32_t a[2][4];
            #pragma unroll
            for (int mi = 0; mi < 2; mi++) {
                const float* base = As + (wm * 32 + mi * 16 + g) * 36 + kk * 8 + tg;
                a[mi][0] = fb(base[0]);
                a[mi][1] = fb(base[8 * 36]);
                a[mi][2] = fb(base[4]);
                a[mi][3] = fb(base[8 * 36 + 4]);
            }
            #pragma unroll
            for (int ni = 0; ni < 8; ni++) {
                const float* bbase = Bs + (wn * 64 + ni * 8 + g) * 36 + kk * 8 + tg;
                uint32_t b0 = fb(bbase[0]);
                uint32_t b1 = fb(bbase[4]);
                mma8(acc[0][ni], a[0], b0, b1);
                mma8(acc[1][ni], a[1], b0, b1);
            }
        }
        __syncthreads();
        st = st + 1 >= 3 ? 0 : st + 1;
    }

    // epilogue: scatter with bias
    #pragma unroll
    for (int mi = 0; mi < 2; mi++) {
        int m = m0 + wm * 32 + mi * 16 + g;
        #pragma unroll
        for (int ni = 0; ni < 8; ni++) {
            int n = n0 + wn * 64 + ni * 8 + tg * 2;
            float2 bs2 = *(const float2*)(bias + n);
            #pragma unroll
            for (int half = 0; half < 2; half++) {
                int mm = m + half * 8;
                float x = acc[mi][ni][half * 2 + 0] + bs2.x;
                float y = acc[mi][ni][half * 2 + 1] + bs2.y;
                int b_ = mm >> 11, nn = mm & 2047;
                if (mode == 0) {
                    int h = n >> 6, hd = n & 63;
                    *(float2*)(g_q + (((size_t)(b_*NHEADS+h))*NSEQ+nn)*HDIM + hd) =
                        make_float2(f2tf(x * 0.125f), f2tf(y * 0.125f));
                } else if (mode == 1) {
                    int h = n >> 6, hd = n & 63;
                    *(float2*)(g_k + (((size_t)(b_*NHEADS+h))*NSEQ+nn)*HDIM + hd) =
                        make_float2(f2tf(x), f2tf(y));
                } else if (mode == 2) {
                    int e = n >> 7, d2 = n & 127;
                    *(float2*)(g_v + (((size_t)(b_*NEFF+e))*NSEQ+nn)*HD2 + d2) =
                        make_float2(x, y);
                } else {
                    *(float2*)(outp + (size_t)mm * DIMC + n) = make_float2(x, y);
                }
            }
        }
    }
}

// ---------------- flash attention, tf32 mma.sync, 8 warps -------------------
// Br=128 q-rows, Bc=64 keys, 256 threads; warp = 16-row stripe (1 m-atom).
// K and V double-buffered via cp.async; Q cp.async in prologue.
__global__ __launch_bounds__(256, 1) void flash_kernel()
{
    extern __shared__ float sm[];
    float* Qs = sm;                     // [128][68]
    float* Ks = Qs + 128 * 68;          // [2][64][68]
    float* Vs = Ks + 2 * 64 * 68;       // [2][64][136]
    float* Ps = Vs + 2 * 64 * 136;      // [128][68]

    int qt = blockIdx.x;                // 0..15
    int bh = blockIdx.y;                // 0..31
    int b_ = bh >> 4, h = bh & 15, e = h >> 1;

    const float* Qg = g_q + ((size_t)bh * NSEQ + qt * 128) * HDIM;
    const float* Kg = g_k + (size_t)bh * NSEQ * HDIM;
    const float* Vg = g_v + ((size_t)(b_ * NEFF + e)) * NSEQ * HD2;

    int tid = threadIdx.x, wid = tid >> 5, lane = tid & 31;
    int g = lane >> 2, tg = lane & 3;
    uint32_t qbase = smem_u32(Qs);
    uint32_t kbase = smem_u32(Ks);
    uint32_t vbase = smem_u32(Vs);

    // ---- prologue: Q + K0 + V0 via cp.async (group 0)
    #pragma unroll
    for (int i = 0; i < 8; i++) {
        int idx = tid + i * 256;
        int row = idx >> 4, c4 = (idx & 15) * 4;
        CP_ASYNC16(qbase + (uint32_t)(row * 68 + c4) * 4u, Qg + (size_t)row * HDIM + c4);
    }
    #pragma unroll
    for (int i = 0; i < 4; i++) {
        int idx = tid + i * 256;
        int row = idx >> 4, c4 = (idx & 15) * 4;
        CP_ASYNC16(kbase + (uint32_t)(row * 68 + c4) * 4u, Kg + (size_t)row * HDIM + c4);
    }
    #pragma unroll
    for (int i = 0; i < 8; i++) {
        int idx = tid + i * 256;
        int row = idx >> 5, c4 = (idx & 31) * 4;
        CP_ASYNC16(vbase + (uint32_t)(row * 136 + c4) * 4u, Vg + (size_t)row * HD2 + c4);
    }
    CP_COMMIT();

    float o[16][4];
    #pragma unroll
    for (int ni = 0; ni < 16; ni++)
        #pragma unroll
        for (int j = 0; j < 4; j++) o[ni][j] = 0.f;
    float mrun[2] = {-1e30f, -1e30f};
    float lrun[2] = {0.f, 0.f};

    for (int kt = 0; kt < 32; kt++) {
        int buf = kt & 1;
        // issue next K/V tiles into other buffer
        if (kt + 1 < 32) {
            uint32_t kb = kbase + (uint32_t)((buf ^ 1) * 64 * 68) * 4u;
            uint32_t vb = vbase + (uint32_t)((buf ^ 1) * 64 * 136) * 4u;
            #pragma unroll
            for (int i = 0; i < 4; i++) {
                int idx = tid + i * 256;
                int row = idx >> 4, c4 = (idx & 15) * 4;
                CP_ASYNC16(kb + (uint32_t)(row * 68 + c4) * 4u,
                           Kg + (size_t)((kt + 1) * 64 + row) * HDIM + c4);
            }
            #pragma unroll
            for (int i = 0; i < 8; i++) {
                int idx = tid + i * 256;
                int row = idx >> 5, c4 = (idx & 31) * 4;
                CP_ASYNC16(vb + (uint32_t)(row * 136 + c4) * 4u,
                           Vg + (size_t)((kt + 1) * 64 + row) * HD2 + c4);
            }
        }
        CP_COMMIT();
        CP_WAIT1();
        __syncthreads();

        // ---- S = Q K^T  (warp rows wid*16..+16, cols 0..64)
        const float* Kb = Ks + buf * 64 * 68;
        float s[8][4];
        #pragma unroll
        for (int ni = 0; ni < 8; ni++)
            #pragma unroll
            for (int j = 0; j < 4; j++) s[ni][j] = 0.f;
        #pragma unroll
        for (int kk = 0; kk < 8; kk++) {
            uint32_t a[4];
            const float* base = Qs + (wid * 16 + g) * 68 + kk * 8 + tg;
            a[0] = fb(base[0]);
            a[1] = fb(base[8 * 68]);
            a[2] = fb(base[4]);
            a[3] = fb(base[8 * 68 + 4]);
            #pragma unroll
            for (int ni = 0; ni < 8; ni++) {
                const float* bbase = Kb + (ni * 8 + g) * 68 + kk * 8 + tg;
                uint32_t b0 = fb(bbase[0]);
                uint32_t b1 = fb(bbase[4]);
                mma8(s[ni], a, b0, b1);
            }
        }

        // ---- online softmax (rows g and g+8; reduce over tg quad)
        #pragma unroll
        for (int half = 0; half < 2; half++) {
            float mx = -1e30f;
            #pragma unroll
            for (int ni = 0; ni < 8; ni++) {
                mx = fmaxf(mx, s[ni][half * 2 + 0]);
                mx = fmaxf(mx, s[ni][half * 2 + 1]);
            }
            mx = fmaxf(mx, __shfl_xor_sync(0xffffffffu, mx, 1));
            mx = fmaxf(mx, __shfl_xor_sync(0xffffffffu, mx, 2));
            float mnew = fmaxf(mrun[half], mx);
            float alpha = exp2f((mrun[half] - mnew) * L2E);
            float sum = 0.f;
            #pragma unroll
            for (int ni = 0; ni < 8; ni++) {
                float p0 = exp2f((s[ni][half * 2 + 0] - mnew) * L2E);
                float p1 = exp2f((s[ni][half * 2 + 1] - mnew) * L2E);
                s[ni][half * 2 + 0] = p0;
                s[ni][half * 2 + 1] = p1;
                sum += p0 + p1;
            }
            sum += __shfl_xor_sync(0xffffffffu, sum, 1);
            sum += __shfl_xor_sync(0xffffffffu, sum, 2);
            lrun[half] = lrun[half] * alpha + sum;
            mrun[half] = mnew;
            #pragma unroll
            for (int ni = 0; ni < 16; ni++) {
                o[ni][half * 2 + 0] *= alpha;
                o[ni][half * 2 + 1] *= alpha;
            }
            int r = wid * 16 + g + half * 8;
            #pragma unroll
            for (int ni = 0; ni < 8; ni++) {
                *(float2*)(Ps + r * 68 + ni * 8 + tg * 2) =
                    make_float2(f2tf(s[ni][half * 2 + 0]),
                                f2tf(s[ni][half * 2 + 1]));
            }
        }
        __syncwarp();

        // ---- O += P V  (P warp-private; V raw bits as tf32)
        const float* Vb = Vs + buf * 64 * 136;
        #pragma unroll
        for (int kk = 0; kk < 8; kk++) {
            uint32_t a[4];
            const float* base = Ps + (wid * 16 + g) * 68 + kk * 8 + tg;
            a[0] = fb(base[0]);
            a[1] = fb(base[8 * 68]);
            a[2] = fb(base[4]);
            a[3] = fb(base[8 * 68 + 4]);
            #pragma unroll
            for (int ni = 0; ni < 16; ni++) {
                const float* bbase = Vb + (kk * 8 + tg) * 136 + ni * 8 + g;
                uint32_t b0 = fb(bbase[0]);
                uint32_t b1 = fb(bbase[4 * 136]);
                mma8(o[ni], a, b0, b1);
            }
        }
        __syncthreads();
    }

    // epilogue
    float* Og = g_attn + ((size_t)bh * NSEQ + qt * 128) * HD2;
    #pragma unroll
    for (int half = 0; half < 2; half++) {
        float inv = 1.f / lrun[half];
        int r = wid * 16 + g + half * 8;
        #pragma unroll
        for (int ni = 0; ni < 16; ni++) {
            *(float2*)(Og + (size_t)r * HD2 + ni * 8 + tg * 2) =
                make_float2(o[ni][half * 2 + 0] * inv,
                            o[ni][half * 2 + 1] * inv);
        }
    }
}

// ---------------- combine: o0 - lam*o1, RMSNorm(128), *w*0.2, tf32-round ----
__global__ __launch_bounds__(128) void combine_kernel(const float* __restrict__ norm_w)
{
    int idx = blockIdx.x;
    int n   = idx & (NSEQ - 1);
    int be  = idx >> 11;
    int b_  = be >> 3, e = be & 7;
    int d   = threadIdx.x;
    float lam = g_lambda;

    size_t base0 = (((size_t)(b_ * NHEADS + 2 * e    )) * NSEQ + n) * HD2;
    size_t base1 = (((size_t)(b_ * NHEADS + 2 * e + 1)) * NSEQ + n) * HD2;
    float xv = g_attn[base0 + d] - lam * g_attn[base1 + d];

    float ss = xv * xv;
    #pragma unroll
    for (int off = 16; off > 0; off >>= 1)
        ss += __shfl_xor_sync(0xffffffffu, ss, off);
    __shared__ float red[4];
    if ((d & 31) == 0) red[d >> 5] = ss;
    __syncthreads();
    float tot = red[0] + red[1] + red[2] + red[3];
    float rms = rsqrtf(tot * (1.0f / HD2) + 1e-5f);

    g_comb[((size_t)(b_ * NSEQ + n)) * DIMC + e * HD2 + d] =
        f2tf(xv * rms * norm_w[d] * 0.2f);
}

// ---------------- launch -----------------------------------------------------
extern "C" void kernel_launch(void* const* d_in, const int* in_sizes, int n_in,
                              void* d_out, int out_size)
{
    const float* x      = (const float*)d_in[0];
    const float* Wq     = (const float*)d_in[1];
    const float* bq     = (const float*)d_in[2];
    const float* Wk     = (const float*)d_in[3];
    const float* bk     = (const float*)d_in[4];
    const float* Wv     = (const float*)d_in[5];
    const float* bv     = (const float*)d_in[6];
    const float* Wo     = (const float*)d_in[7];
    const float* bo     = (const float*)d_in[8];
    const float* norm_w = (const float*)d_in[9];
    const float* lq1    = (const float*)d_in[10];
    const float* lk1    = (const float*)d_in[11];
    const float* lq2    = (const float*)d_in[12];
    const float* lk2    = (const float*)d_in[13];
    float* out = (float*)d_out;

    lambda_kernel<<<1, 32>>>(lq1, lk1, lq2, lk2);

    // pre-round inputs to tf32 (one-time; GEMMs then cp.async raw)
    float* xr = nullptr; cudaGetSymbolAddress((void**)&xr, g_xr);
    float* wr = nullptr; cudaGetSymbolAddress((void**)&wr, g_wr);
    round_kernel<<<MTOT * DIMC / 1024, 256>>>(x,  xr);
    round_kernel<<<DIMC * DIMC / 1024, 256>>>(Wq, wr + 0 * DIMC * DIMC);
    round_kernel<<<DIMC * DIMC / 1024, 256>>>(Wk, wr + 1 * DIMC * DIMC);
    round_kernel<<<DIMC * DIMC / 1024, 256>>>(Wv, wr + 2 * DIMC * DIMC);
    round_kernel<<<DIMC * DIMC / 1024, 256>>>(Wo, wr + 3 * DIMC * DIMC);

    int gemm_smem = 3 * 2 * SSTR * (int)sizeof(float);   // 110,592 B
    cudaFuncSetAttribute(gemm_mma_kernel, cudaFuncAttributeMaxDynamicSharedMemorySize, gemm_smem);

    dim3 gg(DIMC / 128, MTOT / 128);   // (8, 32)
    gemm_mma_kernel<<<gg, 256, gemm_smem>>>(xr, wr + 0 * DIMC * DIMC, bq, nullptr, 0);
    gemm_mma_kernel<<<gg, 256, gemm_smem>>>(xr, wr + 1 * DIMC * DIMC, bk, nullptr, 1);
    gemm_mma_kernel<<<gg, 256, gemm_smem>>>(xr, wr + 2 * DIMC * DIMC, bv, nullptr, 2);

    int flash_smem = (128 * 68 + 2 * 64 * 68 + 2 * 64 * 136 + 128 * 68) * (int)sizeof(float); // 174,080
    cudaFuncSetAttribute(flash_kernel, cudaFuncAttributeMaxDynamicSharedMemorySize, flash_smem);
    flash_kernel<<<dim3(NSEQ / 128, NB * NHEADS), 256, flash_smem>>>();

    combine_kernel<<<NB * NEFF * NSEQ, 128>>>(norm_w);

    gemm_mma_kernel<<<gg, 256, gemm_smem>>>(nullptr, wr + 3 * DIMC * DIMC, bo, out, 3);
}